// round 4
// baseline (speedup 1.0000x reference)
#include <cuda_runtime.h>
#include <mma.h>

using namespace nvcuda;

// ---------------------------------------------------------------------------
// RLFrameSelector: B=32, T=2048, F=512, U=128, k=64
// Score pass: wmma tf32 double-split GEMM (fp32-accurate), HMMA path
// (compute_100 non-'a' target: tcgen05 unavailable on this bench).
// ---------------------------------------------------------------------------

#define B_   32
#define T_   2048
#define F_   512
#define U_   128
#define K_   64
#define NFRAMES (B_ * T_)        // 65536
#define NEG_BIG_F (-1.0e9f)

static __device__ float         g_scores[NFRAMES];
static __device__ unsigned char g_sel[NFRAMES];
static __device__ float         g_Whi[F_ * U_];   // [k][u] tf32-high
static __device__ float         g_Wlo[F_ * U_];   // [k][u] tf32-low

// ---- helpers --------------------------------------------------------------
__device__ __forceinline__ float tf32_rna(float v) {
    unsigned u;
    asm("cvt.rna.tf32.f32 %0, %1;" : "=r"(u) : "f"(v));
    return __uint_as_float(u);
}
__device__ __forceinline__ void cp_async16(void* dst_smem, const void* src_g) {
    unsigned d;
    asm("{ .reg .u64 t; cvta.to.shared.u64 t, %1; cvt.u32.u64 %0, t; }"
        : "=r"(d) : "l"(dst_smem));
    asm volatile("cp.async.ca.shared.global [%0], [%1], 16;"
                 :: "r"(d), "l"(src_g) : "memory");
}
__device__ __forceinline__ void cp_commit() {
    asm volatile("cp.async.commit_group;" ::: "memory");
}
__device__ __forceinline__ void cp_wait0() {
    asm volatile("cp.async.wait_group 0;" ::: "memory");
}

// ---------------------------------------------------------------------------
// Pre-pass: split W1[F,U] into tf32 high/low, same [k][u] layout.
// h = rna_tf32(v); l = rna_tf32(v - h)  (v-h exact; dropped residual ~2^-22)
// ---------------------------------------------------------------------------
__global__ void wsplit_kernel(const float* __restrict__ W1)
{
    const int idx = blockIdx.x * 256 + threadIdx.x;   // grid 256 x 256 = 65536
    const float v = W1[idx];
    const float h = tf32_rna(v);
    g_Whi[idx] = h;
    g_Wlo[idx] = tf32_rna(v - h);
}

// ---------------------------------------------------------------------------
// Score pass: per CTA M=128 frames x N=128 u, K=512 in 16 chunks of 32.
// 256 threads / 8 warps; warp w: rows (w&3)*32 (2 tiles), cols (w>>2)*64 (4).
// Double-buffered smem; W staged by cp.async (pre-split), x prefetched to
// regs during MMA and converted afterward. 3 products: hh, hl, lh.
// ---------------------------------------------------------------------------
#define KC     32
#define NCHUNK (F_ / KC)          // 16
#define XLD    40                 // padded x row stride (floats)
#define WLD    136                // padded W row stride (floats)
#define A_SZ   (128 * XLD)        // 5120 floats per buffer
#define W_SZ   (KC * WLD)         // 4352 floats per buffer
// float offsets into dynamic smem
#define OFF_AHI(b) ((b) * A_SZ)
#define OFF_ALO(b) (2 * A_SZ + (b) * A_SZ)
#define OFF_WHI(b) (4 * A_SZ + (b) * W_SZ)
#define OFF_WLO(b) (4 * A_SZ + 2 * W_SZ + (b) * W_SZ)
#define OFF_SMALL  (4 * A_SZ + 4 * W_SZ)              // 37888 floats
#define SMEM_BYTES ((OFF_SMALL + 384) * 4)            // + nz/b1/W2 = 153088 B
#define CLD    136                                    // epilogue C stride

extern __shared__ float S[];

typedef wmma::fragment<wmma::matrix_a, 16, 16, 8, wmma::precision::tf32,
                       wmma::row_major> FragA;
typedef wmma::fragment<wmma::matrix_b, 16, 16, 8, wmma::precision::tf32,
                       wmma::row_major> FragB;
typedef wmma::fragment<wmma::accumulator, 16, 16, 8, float> FragC;

__global__ __launch_bounds__(256, 1) void score_kernel(
    const float* __restrict__ x, const float* __restrict__ b1,
    const float* __restrict__ W2, const float* __restrict__ b2)
{
    const int tid = threadIdx.x;
    const int wid = tid >> 5;
    const long frame0 = (long)blockIdx.x * 128;

    int*   nzs = (int*)(S + OFF_SMALL);
    float* b1s = S + OFF_SMALL + 128;
    float* w2s = S + OFF_SMALL + 256;
    if (tid < 128) {
        nzs[tid] = 0;
        b1s[tid] = b1[tid];
        w2s[tid] = W2[tid];
    }

    // x staging identity: row = tid>>1, half = tid&1 (16 floats per chunk)
    const int row  = tid >> 1;
    const int half = tid & 1;
    const float* xg = x + (frame0 + row) * F_ + half * 16;
    int nzf = 0;

    // ---- prologue: stage chunk 0 into buffer 0 ----
    {
        // W via cp.async (contiguous source: chunk = [32][128] slab)
        const float* wh = g_Whi;            // chunk 0
        const float* wl = g_Wlo;
#pragma unroll
        for (int i = 0; i < 4; i++) {
            const int idx = i * 1024 + tid * 4;         // float index in slab
            const int kr = idx >> 7, cu = idx & 127;
            cp_async16(S + OFF_WHI(0) + kr * WLD + cu, wh + idx);
            cp_async16(S + OFF_WLO(0) + kr * WLD + cu, wl + idx);
        }
        cp_commit();
        // x convert + store
#pragma unroll
        for (int q = 0; q < 4; q++) {
            float4 v = *(const float4*)(xg + q * 4);
            if (v.x != 0.f || v.y != 0.f || v.z != 0.f || v.w != 0.f) nzf = 1;
            float h0 = tf32_rna(v.x), h1 = tf32_rna(v.y),
                  h2 = tf32_rna(v.z), h3 = tf32_rna(v.w);
            const int off = row * XLD + half * 16 + q * 4;
            *(float4*)(S + OFF_AHI(0) + off) = make_float4(h0, h1, h2, h3);
            *(float4*)(S + OFF_ALO(0) + off) =
                make_float4(tf32_rna(v.x - h0), tf32_rna(v.y - h1),
                            tf32_rna(v.z - h2), tf32_rna(v.w - h3));
        }
        cp_wait0();
        __syncthreads();
    }

    const int r0 = (wid & 3) * 32;   // 2 row tiles: r0, r0+16
    const int c0 = (wid >> 2) * 64;  // 4 col tiles: c0 + 16j

    FragC acc[2][4];
#pragma unroll
    for (int i = 0; i < 2; i++)
#pragma unroll
        for (int j = 0; j < 4; j++) wmma::fill_fragment(acc[i][j], 0.0f);

    for (int c = 0; c < NCHUNK; c++) {
        const int buf = c & 1, nb = buf ^ 1;
        const bool have = (c + 1 < NCHUNK);
        float4 xr[4];
        if (have) {
            const float* wh = g_Whi + (c + 1) * KC * U_;
            const float* wl = g_Wlo + (c + 1) * KC * U_;
#pragma unroll
            for (int i = 0; i < 4; i++) {
                const int idx = i * 1024 + tid * 4;
                const int kr = idx >> 7, cu = idx & 127;
                cp_async16(S + OFF_WHI(nb) + kr * WLD + cu, wh + idx);
                cp_async16(S + OFF_WLO(nb) + kr * WLD + cu, wl + idx);
            }
            cp_commit();
#pragma unroll
            for (int q = 0; q < 4; q++)
                xr[q] = *(const float4*)(xg + (c + 1) * KC + q * 4);
        }

        // ---- MMA on buffer `buf` ----
        const float* AH = S + OFF_AHI(buf);
        const float* AL = S + OFF_ALO(buf);
        const float* WH = S + OFF_WHI(buf);
        const float* WL = S + OFF_WLO(buf);
#pragma unroll
        for (int ks = 0; ks < KC / 8; ks++) {
            const int k0 = ks * 8;
            FragA ah[2], al[2];
            FragB bh[4], bl[4];
#pragma unroll
            for (int i = 0; i < 2; i++) {
                wmma::load_matrix_sync(ah[i], AH + (r0 + 16 * i) * XLD + k0, XLD);
                wmma::load_matrix_sync(al[i], AL + (r0 + 16 * i) * XLD + k0, XLD);
            }
#pragma unroll
            for (int j = 0; j < 4; j++) {
                wmma::load_matrix_sync(bh[j], WH + k0 * WLD + c0 + 16 * j, WLD);
                wmma::load_matrix_sync(bl[j], WL + k0 * WLD + c0 + 16 * j, WLD);
            }
#pragma unroll
            for (int i = 0; i < 2; i++)
#pragma unroll
                for (int j = 0; j < 4; j++) {
                    wmma::mma_sync(acc[i][j], ah[i], bh[j], acc[i][j]);
                    wmma::mma_sync(acc[i][j], ah[i], bl[j], acc[i][j]);
                    wmma::mma_sync(acc[i][j], al[i], bh[j], acc[i][j]);
                }
        }

        if (have) {
#pragma unroll
            for (int q = 0; q < 4; q++) {
                float4 v = xr[q];
                if (v.x != 0.f || v.y != 0.f || v.z != 0.f || v.w != 0.f) nzf = 1;
                float h0 = tf32_rna(v.x), h1 = tf32_rna(v.y),
                      h2 = tf32_rna(v.z), h3 = tf32_rna(v.w);
                const int off = row * XLD + half * 16 + q * 4;
                *(float4*)(S + OFF_AHI(nb) + off) = make_float4(h0, h1, h2, h3);
                *(float4*)(S + OFF_ALO(nb) + off) =
                    make_float4(tf32_rna(v.x - h0), tf32_rna(v.y - h1),
                                tf32_rna(v.z - h2), tf32_rna(v.w - h3));
            }
            cp_wait0();
        }
        __syncthreads();
    }

    // ---- epilogue: C -> smem (aliases A buffers), relu + dot(W2) ----
    if (nzf) nzs[row] = 1;      // benign same-value race
    __syncthreads();            // also: all MMA reads of smem tiles complete

    float* C = S;               // 128 x CLD floats = 69632 B <= A region 81920 B
#pragma unroll
    for (int i = 0; i < 2; i++)
#pragma unroll
        for (int j = 0; j < 4; j++)
            wmma::store_matrix_sync(C + (r0 + 16 * i) * CLD + (c0 + 16 * j),
                                    acc[i][j], CLD, wmma::mem_row_major);
    __syncthreads();

    if (tid < 128) {
        const float* crow = C + tid * CLD;
        float a = 0.f;
#pragma unroll
        for (int u = 0; u < U_; u++) {
            float h = crow[u] + b1s[u];
            h = fmaxf(h, 0.f);
            a = fmaf(h, w2s[u], a);
        }
        g_scores[frame0 + tid] = nzs[tid] ? (a + b2[0]) : NEG_BIG_F;
    }
}

// ---------------------------------------------------------------------------
// Pass 2: per-row top-64 via 64x iterative argmax (known-good).
// Key = (sortable score, 2047-idx): stable lowest-index tie-break.
// ---------------------------------------------------------------------------
__global__ __launch_bounds__(256) void topk_kernel()
{
    __shared__ float s[T_];
    __shared__ unsigned long long red[8];
    const int row = blockIdx.x;
    const int tid = threadIdx.x;
    const float* sc = g_scores + row * T_;

    for (int i = tid; i < T_; i += 256) s[i] = sc[i];
    for (int i = tid; i < T_; i += 256) g_sel[row * T_ + i] = 0;
    __syncthreads();

    for (int it = 0; it < K_; it++) {
        unsigned long long best = 0ull;
#pragma unroll
        for (int j = 0; j < T_ / 256; j++) {
            const int i = tid + j * 256;
            const float v = s[i];
            unsigned u = __float_as_uint(v);
            u = (u & 0x80000000u) ? ~u : (u | 0x80000000u);
            const unsigned long long key =
                ((unsigned long long)u << 32) | (unsigned)(T_ - 1 - i);
            if (key > best) best = key;
        }
#pragma unroll
        for (int off = 16; off > 0; off >>= 1) {
            unsigned long long o = __shfl_down_sync(0xffffffffu, best, off);
            if (o > best) best = o;
        }
        if ((tid & 31) == 0) red[tid >> 5] = best;
        __syncthreads();
        if (tid == 0) {
            unsigned long long b = red[0];
#pragma unroll
            for (int w = 1; w < 8; w++) if (red[w] > b) b = red[w];
            const int idx = (T_ - 1) - (int)(b & 0xffffffffu);
            g_sel[row * T_ + idx] = 1;
            s[idx] = -__int_as_float(0x7f800000);
        }
        __syncthreads();
    }
}

// ---------------------------------------------------------------------------
// Pass 3: out = sel ? x : 0 (known-good, HBM-bound).
// ---------------------------------------------------------------------------
__global__ __launch_bounds__(256) void output_kernel(
    const float4* __restrict__ x4, float4* __restrict__ out4)
{
    const long gid = (long)blockIdx.x * 256 + threadIdx.x;
    const int frame = (int)(gid >> 7);
    float4 v = make_float4(0.f, 0.f, 0.f, 0.f);
    if (g_sel[frame]) v = x4[gid];
    out4[gid] = v;
}

// ---------------------------------------------------------------------------
extern "C" void kernel_launch(void* const* d_in, const int* in_sizes, int n_in,
                              void* d_out, int out_size)
{
    (void)in_sizes; (void)n_in;
    const float* x  = (const float*)d_in[0];
    const float* W1 = (const float*)d_in[1];
    const float* b1 = (const float*)d_in[2];
    const float* W2 = (const float*)d_in[3];
    const float* b2 = (const float*)d_in[4];
    // d_in[5] is k (fixed at 64 by problem spec)

    cudaFuncSetAttribute(score_kernel,
                         cudaFuncAttributeMaxDynamicSharedMemorySize, SMEM_BYTES);

    wsplit_kernel<<<F_ * U_ / 256, 256>>>(W1);
    score_kernel<<<NFRAMES / 128, 256, SMEM_BYTES>>>(x, b1, W2, b2);
    topk_kernel<<<B_, 256>>>();
    const int n4 = out_size / 4;
    output_kernel<<<n4 / 256, 256>>>((const float4*)x, (float4*)d_out);
}